// round 3
// baseline (speedup 1.0000x reference)
#include <cuda_runtime.h>
#include <cuda_bf16.h>
#include <cstdint>

#define Hn    250       // hidden units
#define Bn    256       // batch
#define Tn    512       // time steps
#define Gn    1000      // 4*H gate rows
#define HP    256       // padded hidden stride in h buffers
#define KP    252       // padded K for recurrent GEMM
#define KCn   63        // KP/4 chunks

// ---------------- scratch (device globals; zero-initialized at load) ----------------
__device__ float    g_xg[(size_t)Tn * Bn * Gn];        // 524 MB input-gate contributions (reused for both layers)
__device__ float    g_h1[(size_t)(Tn + 1) * Bn * HP];  // layer-0 hidden states, slice 0 = zeros (never written)
__device__ float    g_h2[(size_t)(Tn + 1) * Bn * HP];  // layer-1 hidden states
__device__ unsigned g_cnt[2];
__device__ unsigned g_flag[2];

// ---------------- helpers ----------------
__device__ __forceinline__ float sigf(float x) { return 1.f / (1.f + __expf(-x)); }
__device__ __forceinline__ float tanhfast(float x) { return 1.f - 2.f / (__expf(2.f * x) + 1.f); }

// Fill transposed, gate-interleaved weight tile into smem:
// sW[k*64 + m], m = u_local*4 + g  <-  W[g*H + u0 + u_local][k], zero-padded.
__device__ void fill_WT(float* sW, const float* __restrict__ W, int u0, int Kreal, int kc_n) {
    int total = 64 * kc_n;
    for (int i = threadIdx.x; i < total; i += blockDim.x) {
        int m  = i / kc_n;
        int kc = i - m * kc_n;
        int k  = kc * 4;
        int g  = m & 3;
        int u  = u0 + (m >> 2);
        float4 v = make_float4(0.f, 0.f, 0.f, 0.f);
        if (u < Hn) {
            const float* src = W + (size_t)(g * Hn + u) * Kreal + k;
            if (k + 0 < Kreal) v.x = src[0];
            if (k + 1 < Kreal) v.y = src[1];
            if (k + 2 < Kreal) v.z = src[2];
            if (k + 3 < Kreal) v.w = src[3];
        }
        sW[(k + 0) * 64 + m] = v.x;
        sW[(k + 1) * 64 + m] = v.y;
        sW[(k + 2) * 64 + m] = v.z;
        sW[(k + 3) * 64 + m] = v.w;
    }
}

__global__ void k_reset() {
    if (threadIdx.x < 2) { g_cnt[threadIdx.x] = 0u; g_flag[threadIdx.x] = 0u; }
}

// ---------------- input-contribution GEMM ----------------
// out xg[r][m] for r = t*256+b (row-major, Gn cols, m gate-interleaved), bias baked in.
// amode 0: A = x, rows mapped (b*T + t), K=40.  amode 1: A = g_h1, row = r+256, K=250.
__global__ void __launch_bounds__(256, 1)
k_xgemm(const float* __restrict__ A_in, const float* __restrict__ Wih,
        const float* __restrict__ bih, const float* __restrict__ bhh,
        int amode, int Kreal, int kc_n) {
    extern __shared__ float smem[];
    float* sW = smem;                    // kc_n*4 * 64
    float* sA = sW + (size_t)kc_n * 4 * 64; // 64 * 260
    float* sB = sA + 64 * 260;           // 64 bias
    int tid = threadIdx.x;
    int u0 = blockIdx.y * 16;
    int rbase = blockIdx.x * 64;

    fill_WT(sW, Wih, u0, Kreal, kc_n);
    if (tid < 64) {
        int g = tid & 3, u = u0 + (tid >> 2);
        sB[tid] = (u < Hn) ? (bih[g * Hn + u] + bhh[g * Hn + u]) : 0.f;
    }
    if (amode == 1) {
        const float4* src = (const float4*)(g_h1 + ((size_t)rbase + Bn) * HP);
        for (int i = tid; i < 64 * 64; i += 256) {
            int row = i >> 6, c4 = i & 63;
            *(float4*)&sA[row * 260 + c4 * 4] = __ldg(src + (size_t)row * 64 + c4);
        }
    } else {
        for (int i = tid; i < 64 * 10; i += 256) {
            int row = i / 10, c4 = i - row * 10;
            int r = rbase + row;
            int tt = r >> 8, b = r & 255;
            *(float4*)&sA[row * 260 + c4 * 4] =
                __ldg((const float4*)(A_in + ((size_t)b * Tn + tt) * 40 + c4 * 4));
        }
    }
    __syncthreads();

    int q = tid & 15, rg = tid >> 4;
    int rl = rg * 4;
    float4 acc0 = make_float4(0.f,0.f,0.f,0.f);
    float4 acc1 = acc0, acc2 = acc0, acc3 = acc0;

    #pragma unroll 3
    for (int kc = 0; kc < kc_n; ++kc) {
        int k = kc * 4;
        float4 w0 = *(const float4*)&sW[(k + 0) * 64 + 4 * q];
        float4 w1 = *(const float4*)&sW[(k + 1) * 64 + 4 * q];
        float4 w2 = *(const float4*)&sW[(k + 2) * 64 + 4 * q];
        float4 w3 = *(const float4*)&sW[(k + 3) * 64 + 4 * q];
#define XACC(ACC, ROW)                                                              \
        {                                                                           \
            float4 av = *(const float4*)&sA[(rl + ROW) * 260 + k];                  \
            ACC.x = fmaf(w0.x, av.x, ACC.x); ACC.y = fmaf(w0.y, av.x, ACC.y);       \
            ACC.z = fmaf(w0.z, av.x, ACC.z); ACC.w = fmaf(w0.w, av.x, ACC.w);       \
            ACC.x = fmaf(w1.x, av.y, ACC.x); ACC.y = fmaf(w1.y, av.y, ACC.y);       \
            ACC.z = fmaf(w1.z, av.y, ACC.z); ACC.w = fmaf(w1.w, av.y, ACC.w);       \
            ACC.x = fmaf(w2.x, av.z, ACC.x); ACC.y = fmaf(w2.y, av.z, ACC.y);       \
            ACC.z = fmaf(w2.z, av.z, ACC.z); ACC.w = fmaf(w2.w, av.z, ACC.w);       \
            ACC.x = fmaf(w3.x, av.w, ACC.x); ACC.y = fmaf(w3.y, av.w, ACC.y);       \
            ACC.z = fmaf(w3.z, av.w, ACC.z); ACC.w = fmaf(w3.w, av.w, ACC.w);       \
        }
        XACC(acc0, 0) XACC(acc1, 1) XACC(acc2, 2) XACC(acc3, 3)
#undef XACC
    }

    int u = u0 + q;
    if (u < Hn) {
        float4 bv = *(const float4*)&sB[4 * q];
#define XOUT(ACC, ROW)                                                              \
        {                                                                           \
            float4 o;                                                               \
            o.x = ACC.x + bv.x; o.y = ACC.y + bv.y;                                 \
            o.z = ACC.z + bv.z; o.w = ACC.w + bv.w;                                 \
            *(float4*)(g_xg + ((size_t)(rbase + rl + ROW)) * Gn + u * 4) = o;       \
        }
        XOUT(acc0, 0) XOUT(acc1, 1) XOUT(acc2, 2) XOUT(acc3, 3)
#undef XOUT
    }
}

// ---------------- persistent recurrent kernel ----------------
// 128 CTAs = 16 unit-tiles (16 units, last ragged) x 8 batch-tiles (32).
// Per thread: unit q = tid&15, cols c0,c0+1 (c0 = (tid>>4)*2); cell state in regs.
__global__ void __launch_bounds__(256, 1)
k_rec(const float* __restrict__ Whh, int layer) {
    extern __shared__ float smem[];
    float* sW = smem;             // KP*64
    float* sH = smem + KP * 64;   // 32*260

    float* hb = layer ? g_h2 : g_h1;
    const float* xg = g_xg;
    unsigned* cnt = &g_cnt[layer];
    unsigned* flg = &g_flag[layer];

    int tid = threadIdx.x;
    int ut = blockIdx.x & 15, bt = blockIdx.x >> 4;
    int u0 = ut * 16, b0 = bt * 32;
    int q = tid & 15, cg = tid >> 4, c0 = cg * 2;
    int u = u0 + q;
    bool valid = (u < Hn);

    fill_WT(sW, Whh, u0, Hn, KCn);

    float cv0 = 0.f, cv1 = 0.f;
    __syncthreads();

    for (int t = 0; t < Tn; ++t) {
        // stage h(t) tile [32 x 256] into smem (L2-coherent reads)
        const float4* hsrc = (const float4*)(hb + ((size_t)t * Bn + b0) * HP);
        for (int i = tid; i < 32 * 64; i += 256) {
            int row = i >> 6, c4 = i & 63;
            float4 v = __ldcg(hsrc + (size_t)row * 64 + c4);
            *(float4*)&sH[row * 260 + c4 * 4] = v;
        }
        __syncthreads();

        float4 a0 = make_float4(0.f,0.f,0.f,0.f);
        float4 a1 = a0;
        const float* hA = &sH[(c0 + 0) * 260];
        const float* hB = &sH[(c0 + 1) * 260];

        #pragma unroll 9
        for (int kc = 0; kc < KCn; ++kc) {
            int k = kc * 4;
            float4 w0 = *(const float4*)&sW[(k + 0) * 64 + 4 * q];
            float4 w1 = *(const float4*)&sW[(k + 1) * 64 + 4 * q];
            float4 w2 = *(const float4*)&sW[(k + 2) * 64 + 4 * q];
            float4 w3 = *(const float4*)&sW[(k + 3) * 64 + 4 * q];
            float4 ha = *(const float4*)&hA[k];
            float4 hbv = *(const float4*)&hB[k];
#define RACC(ACC, HV)                                                               \
            ACC.x = fmaf(w0.x, HV.x, ACC.x); ACC.y = fmaf(w0.y, HV.x, ACC.y);       \
            ACC.z = fmaf(w0.z, HV.x, ACC.z); ACC.w = fmaf(w0.w, HV.x, ACC.w);       \
            ACC.x = fmaf(w1.x, HV.y, ACC.x); ACC.y = fmaf(w1.y, HV.y, ACC.y);       \
            ACC.z = fmaf(w1.z, HV.y, ACC.z); ACC.w = fmaf(w1.w, HV.y, ACC.w);       \
            ACC.x = fmaf(w2.x, HV.z, ACC.x); ACC.y = fmaf(w2.y, HV.z, ACC.y);       \
            ACC.z = fmaf(w2.z, HV.z, ACC.z); ACC.w = fmaf(w2.w, HV.z, ACC.w);       \
            ACC.x = fmaf(w3.x, HV.w, ACC.x); ACC.y = fmaf(w3.y, HV.w, ACC.y);       \
            ACC.z = fmaf(w3.z, HV.w, ACC.z); ACC.w = fmaf(w3.w, HV.w, ACC.w);
            RACC(a0, ha)
            RACC(a1, hbv)
#undef RACC
        }

        // pointwise LSTM cell for the 2 owned (batch, unit) cells
        size_t r0 = (size_t)t * Bn + b0 + c0;
        float4 x0 = make_float4(0.f,0.f,0.f,0.f), x1 = x0;
        if (valid) {
            x0 = __ldg((const float4*)(xg + r0 * Gn + u * 4));
            x1 = __ldg((const float4*)(xg + (r0 + 1) * Gn + u * 4));
        }
        {
            float iv = sigf(a0.x + x0.x);
            float fv = sigf(a0.y + x0.y);
            float gv = tanhfast(a0.z + x0.z);
            float ov = sigf(a0.w + x0.w);
            cv0 = fv * cv0 + iv * gv;
            float hv = ov * tanhfast(cv0);
            if (valid)
                __stcg(hb + (((size_t)(t + 1) * Bn + b0 + c0) * HP + u), hv);
        }
        {
            float iv = sigf(a1.x + x1.x);
            float fv = sigf(a1.y + x1.y);
            float gv = tanhfast(a1.z + x1.z);
            float ov = sigf(a1.w + x1.w);
            cv1 = fv * cv1 + iv * gv;
            float hv = ov * tanhfast(cv1);
            if (valid)
                __stcg(hb + (((size_t)(t + 1) * Bn + b0 + c0 + 1) * HP + u), hv);
        }

        // ---- grid barrier (sense-epoch, one per step) ----
        __syncthreads();
        if (tid == 0) {
            __threadfence();
            unsigned old = atomicAdd(cnt, 1u);
            unsigned epoch = (unsigned)(t + 1);
            if (old == 127u) {
                atomicExch(cnt, 0u);
                asm volatile("st.release.gpu.b32 [%0], %1;" :: "l"(flg), "r"(epoch) : "memory");
            } else {
                unsigned v;
                do {
                    asm volatile("ld.acquire.gpu.b32 %0, [%1];" : "=r"(v) : "l"(flg) : "memory");
                } while (v < epoch);
            }
        }
        __syncthreads();
    }
}

// ---------------- output head ----------------
__global__ void __launch_bounds__(256, 1)
k_head(const float* __restrict__ Wl, const float* __restrict__ bl, float* __restrict__ out) {
    __shared__ float sw[256];
    int tid = threadIdx.x;
    sw[tid] = (tid < Hn) ? Wl[tid] : 0.f;
    __syncthreads();
    int warp = tid >> 5, lane = tid & 31;
    int r = blockIdx.x * 8 + warp;         // r = b*T + t (output order)
    int t = r & (Tn - 1);
    int b = r >> 9;
    const float* hrow = g_h2 + ((size_t)(t + 1) * Bn + b) * HP;
    float p = 0.f;
    #pragma unroll
    for (int j = 0; j < 8; ++j) {
        int k = j * 32 + lane;
        p = fmaf(sw[k], __ldg(hrow + k), p);   // cols 250..255 are zero in both
    }
    #pragma unroll
    for (int off = 16; off; off >>= 1) p += __shfl_xor_sync(0xffffffffu, p, off);
    if (lane == 0) out[r] = 1.f / (1.f + __expf(-(p + bl[0])));
}

// ---------------- launcher ----------------
extern "C" void kernel_launch(void* const* d_in, const int* in_sizes, int n_in,
                              void* d_out, int out_size) {
    const float* x    = (const float*)d_in[0];
    const float* Wih0 = (const float*)d_in[1];
    const float* Whh0 = (const float*)d_in[2];
    const float* bih0 = (const float*)d_in[3];
    const float* bhh0 = (const float*)d_in[4];
    const float* Wih1 = (const float*)d_in[5];
    const float* Whh1 = (const float*)d_in[6];
    const float* bih1 = (const float*)d_in[7];
    const float* bhh1 = (const float*)d_in[8];
    const float* Wlin = (const float*)d_in[9];
    const float* blin = (const float*)d_in[10];
    float* out = (float*)d_out;

    const int smem_rec    = (KP * 64 + 32 * 260) * 4;                 // 97,792 B
    const int smem_gemm1  = (KCn * 4 * 64 + 64 * 260 + 64) * 4;       // 131,328 B
    const int smem_gemm0  = (10 * 4 * 64 + 64 * 260 + 64) * 4;        // 77,056 B

    cudaFuncSetAttribute(k_rec,   cudaFuncAttributeMaxDynamicSharedMemorySize, smem_rec);
    cudaFuncSetAttribute(k_xgemm, cudaFuncAttributeMaxDynamicSharedMemorySize, smem_gemm1);

    k_reset<<<1, 32>>>();

    // layer 0
    k_xgemm<<<dim3(2048, 16), 256, smem_gemm0>>>(x, Wih0, bih0, bhh0, 0, 40, 10);
    k_rec<<<128, 256, smem_rec>>>(Whh0, 0);

    // layer 1
    k_xgemm<<<dim3(2048, 16), 256, smem_gemm1>>>(nullptr, Wih1, bih1, bhh1, 1, Hn, KCn);
    k_rec<<<128, 256, smem_rec>>>(Whh1, 1);

    // head
    k_head<<<16384, 256>>>(Wlin, blin, out);
}